// round 1
// baseline (speedup 1.0000x reference)
#include <cuda_runtime.h>
#include <math.h>

#define B_ 2
#define T_ 2048
#define C_ 1024
#define H_ 16
#define D_ 64
#define M_ (B_*T_)   // 4096

// ---------------- scratch (device globals; no allocation allowed) ----------
__device__ float g_q[B_*H_*T_*D_];     // [B,H,T,D] rotated Q
__device__ float g_k[B_*H_*T_*D_];     // [B,H,T,D] rotated K
__device__ float g_v[B_*H_*T_*D_];     // [B,H,T,D] V
__device__ float g_att[B_*H_*T_*D_];   // [B,H,T,D] attention output
__device__ float g_cos[T_*D_];
__device__ float g_sin[T_*D_];

// ---------------- RoPE tables (fp64-accurate, matches reference convention) -
// reference: inv_freq[i] = 10000^(-2i/64), i in [0,32)
// cos/sin index for dim d uses inv_freq[d mod 32]
__global__ void rope_table_kernel() {
    int idx = blockIdx.x * blockDim.x + threadIdx.x;   // t*64 + d
    if (idx >= T_*D_) return;
    int d = idx & (D_-1);
    int t = idx >> 6;
    int i = d & 31;
    double f = exp(-(double)(2*i) * (9.210340371976184 / 64.0)); // ln(10000)
    double a = (double)t * f;
    g_cos[idx] = (float)cos(a);
    g_sin[idx] = (float)sin(a);
}

// ---------------- tiled SGEMM: C = X @ W^T + b, fused RoPE + head transpose -
#define BM 64
#define BN 64
#define BK 16
#define LDA (BM+4)   // pad: conflict-light stores, 16B-aligned float4 rows

__global__ __launch_bounds__(256) void qkv_gemm_kernel(
    const float* __restrict__ X,
    const float* __restrict__ Wq, const float* __restrict__ Bq,
    const float* __restrict__ Wk, const float* __restrict__ Bk,
    const float* __restrict__ Wv, const float* __restrict__ Bv)
{
    __shared__ float As[BK][LDA];   // [k][m]
    __shared__ float Bs[BK][LDA];   // [k][n]
    const int which = blockIdx.z;
    const float* W    = (which==0) ? Wq : (which==1) ? Wk : Wv;
    const float* bias = (which==0) ? Bq : (which==1) ? Bk : Bv;
    float* dst        = (which==0) ? g_q : (which==1) ? g_k : g_v;

    int tid = threadIdx.x;
    int tx = tid & 15, ty = tid >> 4;
    int m0 = blockIdx.y * BM, n0 = blockIdx.x * BN;

    float acc[4][4] = {};
    for (int k0 = 0; k0 < C_; k0 += BK) {
        #pragma unroll
        for (int l = 0; l < 4; l++) {
            int flat = tid + l*256;           // 1024 elements per tile
            int r = flat >> 4, kk = flat & 15;
            As[kk][r] = X[(m0+r)*C_ + k0 + kk];
            Bs[kk][r] = W[(n0+r)*C_ + k0 + kk];
        }
        __syncthreads();
        #pragma unroll
        for (int kk = 0; kk < BK; kk++) {
            float4 a4 = *(const float4*)&As[kk][ty*4];
            float4 b4 = *(const float4*)&Bs[kk][tx*4];
            float av[4] = {a4.x, a4.y, a4.z, a4.w};
            float bv[4] = {b4.x, b4.y, b4.z, b4.w};
            #pragma unroll
            for (int i = 0; i < 4; i++)
                #pragma unroll
                for (int j = 0; j < 4; j++)
                    acc[i][j] += av[i]*bv[j];
        }
        __syncthreads();
    }

    // epilogue: bias (+RoPE for q,k) and write to [B,H,T,D]
    #pragma unroll
    for (int i = 0; i < 4; i++) {
        int m = m0 + ty*4 + i;
        int b = m >> 11, t = m & (T_-1);
        if (which < 2) {
            #pragma unroll
            for (int jp = 0; jp < 4; jp += 2) {     // pairs (d, d+1)
                int n = n0 + tx*4 + jp;
                int h = n >> 6, d = n & 63;
                float x0 = acc[i][jp]   + bias[n];
                float x1 = acc[i][jp+1] + bias[n+1];
                float c0 = g_cos[t*D_+d],   s0 = g_sin[t*D_+d];
                float c1 = g_cos[t*D_+d+1], s1 = g_sin[t*D_+d+1];
                int base = ((b*H_+h)*T_+t)*D_ + d;
                dst[base]   = x0*c0 - x1*s0;   // out[2i]   = x0*c - x1*s
                dst[base+1] = x1*c1 + x0*s1;   // out[2i+1] = x1*c + x0*s
            }
        } else {
            #pragma unroll
            for (int j = 0; j < 4; j++) {
                int n = n0 + tx*4 + j;
                int h = n >> 6, d = n & 63;
                dst[((b*H_+h)*T_+t)*D_ + d] = acc[i][j] + bias[n];
            }
        }
    }
}

// ---------------- flash attention (fp32, online softmax) -------------------
#define AP 68   // padded row length (16B-aligned rows: 68*4 = 272B)
#define ATTN_SMEM ((4*64*AP + 64*17 + 3*64)*4)   // 74752 bytes

__global__ __launch_bounds__(256) void attn_kernel()
{
    extern __shared__ float smv[];
    float* Qs      = smv;               // [d][m]  64x68
    float* Ks      = Qs + 64*AP;        // [d][n]
    float* Vs      = Ks + 64*AP;        // [n][d]
    float* Ss      = Vs + 64*AP;        // [m][n]  P tile
    float* red     = Ss + 64*AP;        // [64][17] reduction scratch
    float* row_max = red + 64*17;
    float* row_alp = row_max + 64;
    float* row_sum = row_alp + 64;

    int bh = blockIdx.y;
    int q0 = blockIdx.x * 64;
    const float* Q = g_q + bh*(T_*D_);
    const float* K = g_k + bh*(T_*D_);
    const float* V = g_v + bh*(T_*D_);
    int tid = threadIdx.x, tx = tid & 15, ty = tid >> 4;

    for (int f = tid; f < 64*64; f += 256) {
        int m = f >> 6, d = f & 63;
        Qs[d*AP + m] = Q[(q0+m)*D_ + d];
    }
    if (tid < 64) { row_max[tid] = -INFINITY; row_sum[tid] = 0.f; }
    float o[4][4] = {};
    __syncthreads();

    for (int kt = 0; kt < T_/64; kt++) {
        const float* Kt = K + kt*64*D_;
        const float* Vt = V + kt*64*D_;
        for (int f = tid; f < 64*64; f += 256) {
            int n = f >> 6, d = f & 63;
            Ks[d*AP + n] = Kt[n*D_ + d];
            Vs[n*AP + d] = Vt[n*D_ + d];
        }
        __syncthreads();

        // S = (Q K^T) / 8
        float s[4][4] = {};
        #pragma unroll 16
        for (int d = 0; d < 64; d++) {
            float4 a4 = *(const float4*)&Qs[d*AP + ty*4];
            float4 b4 = *(const float4*)&Ks[d*AP + tx*4];
            float av[4] = {a4.x, a4.y, a4.z, a4.w};
            float bv[4] = {b4.x, b4.y, b4.z, b4.w};
            #pragma unroll
            for (int i = 0; i < 4; i++)
                #pragma unroll
                for (int j = 0; j < 4; j++)
                    s[i][j] += av[i]*bv[j];
        }
        #pragma unroll
        for (int i = 0; i < 4; i++)
            #pragma unroll
            for (int j = 0; j < 4; j++)
                s[i][j] *= 0.125f;

        // per-row partial max -> full max + rescale factor
        #pragma unroll
        for (int i = 0; i < 4; i++) {
            float pm = fmaxf(fmaxf(s[i][0], s[i][1]), fmaxf(s[i][2], s[i][3]));
            red[(ty*4+i)*17 + tx] = pm;
        }
        __syncthreads();
        if (tid < 64) {
            float mx = red[tid*17];
            #pragma unroll
            for (int x = 1; x < 16; x++) mx = fmaxf(mx, red[tid*17+x]);
            float om = row_max[tid];
            float nm = fmaxf(om, mx);
            row_alp[tid] = expf(om - nm);   // expf(-inf)=0 on first tile
            row_max[tid] = nm;
        }
        __syncthreads();

        // P = exp(S - m), rescale O, partial row sums
        #pragma unroll
        for (int i = 0; i < 4; i++) {
            int r = ty*4 + i;
            float nm = row_max[r], al = row_alp[r];
            float psum = 0.f;
            #pragma unroll
            for (int j = 0; j < 4; j++) {
                float p = expf(s[i][j] - nm);
                Ss[r*AP + tx*4 + j] = p;
                psum += p;
            }
            red[r*17 + tx] = psum;
            #pragma unroll
            for (int j = 0; j < 4; j++) o[i][j] *= al;
        }
        __syncthreads();
        if (tid < 64) {
            float sum = 0.f;
            #pragma unroll
            for (int x = 0; x < 16; x++) sum += red[tid*17+x];
            row_sum[tid] = row_sum[tid]*row_alp[tid] + sum;
        }

        // O += P @ V
        #pragma unroll 8
        for (int n = 0; n < 64; n++) {
            float4 v4 = *(const float4*)&Vs[n*AP + tx*4];
            float vv[4] = {v4.x, v4.y, v4.z, v4.w};
            float pr[4];
            #pragma unroll
            for (int i = 0; i < 4; i++) pr[i] = Ss[(ty*4+i)*AP + n];
            #pragma unroll
            for (int i = 0; i < 4; i++)
                #pragma unroll
                for (int j = 0; j < 4; j++)
                    o[i][j] += pr[i]*vv[j];
        }
        __syncthreads();   // protect Ks/Vs/Ss/red for next tile; orders row_sum
    }

    #pragma unroll
    for (int i = 0; i < 4; i++) {
        float inv = 1.0f / row_sum[ty*4 + i];
        #pragma unroll
        for (int j = 0; j < 4; j++)
            g_att[(bh*T_ + q0 + ty*4 + i)*D_ + tx*4 + j] = o[i][j]*inv;
    }
}

// ---------------- output projection: Out = att @ Wo^T + bo -----------------
__global__ __launch_bounds__(256) void out_gemm_kernel(
    const float* __restrict__ Wo, const float* __restrict__ Bo,
    float* __restrict__ Out)
{
    __shared__ float As[BK][LDA];
    __shared__ float Bs[BK][LDA];
    int tid = threadIdx.x;
    int tx = tid & 15, ty = tid >> 4;
    int m0 = blockIdx.y * BM, n0 = blockIdx.x * BN;

    float acc[4][4] = {};
    for (int k0 = 0; k0 < C_; k0 += BK) {
        #pragma unroll
        for (int l = 0; l < 4; l++) {
            int flat = tid + l*256;
            int r = flat >> 4, kk = flat & 15;
            int m = m0 + r;
            int k = k0 + kk;
            int b = m >> 11, t = m & (T_-1);
            int h = k >> 6,  d = k & 63;
            As[kk][r] = g_att[((b*H_+h)*T_ + t)*D_ + d];  // gather [B,H,T,D]
            Bs[kk][r] = Wo[(n0+r)*C_ + k];
        }
        __syncthreads();
        #pragma unroll
        for (int kk = 0; kk < BK; kk++) {
            float4 a4 = *(const float4*)&As[kk][ty*4];
            float4 b4 = *(const float4*)&Bs[kk][tx*4];
            float av[4] = {a4.x, a4.y, a4.z, a4.w};
            float bv[4] = {b4.x, b4.y, b4.z, b4.w};
            #pragma unroll
            for (int i = 0; i < 4; i++)
                #pragma unroll
                for (int j = 0; j < 4; j++)
                    acc[i][j] += av[i]*bv[j];
        }
        __syncthreads();
    }
    #pragma unroll
    for (int i = 0; i < 4; i++) {
        int m = m0 + ty*4 + i;
        #pragma unroll
        for (int j = 0; j < 4; j++) {
            int n = n0 + tx*4 + j;
            Out[m*C_ + n] = acc[i][j] + Bo[n];
        }
    }
}

// ---------------- launch ---------------------------------------------------
extern "C" void kernel_launch(void* const* d_in, const int* in_sizes, int n_in,
                              void* d_out, int out_size)
{
    const float* x  = (const float*)d_in[0];
    const float* wq = (const float*)d_in[1];
    const float* bq = (const float*)d_in[2];
    const float* wk = (const float*)d_in[3];
    const float* bk = (const float*)d_in[4];
    const float* wv = (const float*)d_in[5];
    const float* bv = (const float*)d_in[6];
    const float* wo = (const float*)d_in[7];
    const float* bo = (const float*)d_in[8];
    float* out = (float*)d_out;

    cudaFuncSetAttribute(attn_kernel,
                         cudaFuncAttributeMaxDynamicSharedMemorySize, ATTN_SMEM);

    rope_table_kernel<<<(T_*D_ + 255)/256, 256>>>();
    qkv_gemm_kernel<<<dim3(C_/BN, M_/BM, 3), 256>>>(x, wq, bq, wk, bk, wv, bv);
    attn_kernel<<<dim3(T_/64, B_*H_), 256, ATTN_SMEM>>>();
    out_gemm_kernel<<<dim3(C_/BN, M_/BM), 256>>>(wo, bo, out);
}

// round 3
// speedup vs baseline: 2.5978x; 2.5978x over previous
#include <cuda_runtime.h>
#include <math.h>
#include <stdint.h>

#define B_ 2
#define T_ 2048
#define C_ 1024
#define H_ 16
#define D_ 64
#define M_ (B_*T_)   // 4096

// ---------------- scratch (device globals; no allocation allowed) ----------
__device__ float g_q[B_*H_*T_*D_];     // [B,H,T,D] rotated Q
__device__ float g_k[B_*H_*T_*D_];     // [B,H,T,D] rotated K
__device__ float g_v[B_*H_*T_*D_];     // [B,H,T,D] V
__device__ float g_att[B_*H_*T_*D_];   // [B,H,T,D] attention output
__device__ float g_cos[T_*D_];
__device__ float g_sin[T_*D_];

// ---------------- PTX helpers ----------------------------------------------
__device__ __forceinline__ uint32_t f2tf(float f) {
    uint32_t r;
    asm("cvt.rna.tf32.f32 %0, %1;" : "=r"(r) : "f"(f));
    return r;
}

__device__ __forceinline__ void mma_tf32(float* d, const uint32_t* a,
                                         const uint32_t* b, const float* c) {
    asm volatile(
        "mma.sync.aligned.m16n8k8.row.col.f32.tf32.tf32.f32 "
        "{%0,%1,%2,%3}, {%4,%5,%6,%7}, {%8,%9}, {%10,%11,%12,%13};"
        : "=f"(d[0]), "=f"(d[1]), "=f"(d[2]), "=f"(d[3])
        : "r"(a[0]), "r"(a[1]), "r"(a[2]), "r"(a[3]),
          "r"(b[0]), "r"(b[1]),
          "f"(c[0]), "f"(c[1]), "f"(c[2]), "f"(c[3]));
}

__device__ __forceinline__ void cpa16(float* dst, const float* src) {
    uint32_t d = (uint32_t)__cvta_generic_to_shared(dst);
    asm volatile("cp.async.cg.shared.global [%0], [%1], 16;" :: "r"(d), "l"(src));
}
#define CP_COMMIT asm volatile("cp.async.commit_group;")
#define CP_WAIT(n) asm volatile("cp.async.wait_group %0;" :: "n"(n))

// ---------------- RoPE tables ----------------------------------------------
__global__ void rope_table_kernel() {
    int idx = blockIdx.x * blockDim.x + threadIdx.x;
    if (idx >= T_*D_) return;
    int d = idx & (D_-1);
    int t = idx >> 6;
    int i = d & 31;
    double f = exp(-(double)(2*i) * (9.210340371976184 / 64.0));
    double a = (double)t * f;
    g_cos[idx] = (float)cos(a);
    g_sin[idx] = (float)sin(a);
}

// ---------------- QKV GEMM: tf32 mma, 128x128x16 tiles, fused RoPE ---------
#define SA 20   // smem row stride (floats): conflict-free fragment LDS

__global__ __launch_bounds__(256) void qkv_gemm_kernel(
    const float* __restrict__ X,
    const float* __restrict__ Wq, const float* __restrict__ Bq,
    const float* __restrict__ Wk, const float* __restrict__ Bk,
    const float* __restrict__ Wv, const float* __restrict__ Bv)
{
    __shared__ float Xs[2][128*SA];
    __shared__ float Ws[2][128*SA];
    const int which = blockIdx.z;
    const float* W    = (which==0) ? Wq : (which==1) ? Wk : Wv;
    const float* bias = (which==0) ? Bq : (which==1) ? Bk : Bv;
    float* dst        = (which==0) ? g_q : (which==1) ? g_k : g_v;

    int tid = threadIdx.x;
    int lane = tid & 31, warp = tid >> 5;
    int g = lane >> 2, c = lane & 3;
    int wm = warp & 3, wn = warp >> 2;
    int m0 = blockIdx.y * 128, n0 = blockIdx.x * 128;

    float acc[2][8][4] = {};

    // prologue: stage 0
    #pragma unroll
    for (int i = 0; i < 2; i++) {
        int q = tid + i*256; int row = q >> 2, kc = q & 3;
        cpa16(&Xs[0][row*SA + kc*4], X + (m0+row)*C_ + kc*4);
        cpa16(&Ws[0][row*SA + kc*4], W + (n0+row)*C_ + kc*4);
    }
    CP_COMMIT;

    for (int it = 0; it < 64; ++it) {
        int buf = it & 1;
        if (it + 1 < 64) {
            int k0 = (it+1)*16, nb = buf ^ 1;
            #pragma unroll
            for (int i = 0; i < 2; i++) {
                int q = tid + i*256; int row = q >> 2, kc = q & 3;
                cpa16(&Xs[nb][row*SA + kc*4], X + (m0+row)*C_ + k0 + kc*4);
                cpa16(&Ws[nb][row*SA + kc*4], W + (n0+row)*C_ + k0 + kc*4);
            }
            CP_COMMIT;
            CP_WAIT(1);
        } else {
            CP_WAIT(0);
        }
        __syncthreads();

        #pragma unroll
        for (int ks = 0; ks < 2; ks++) {
            int kk = ks*8;
            uint32_t a[2][4], b[8][2];
            #pragma unroll
            for (int mi = 0; mi < 2; mi++) {
                const float* p = &Xs[buf][(wm*32 + mi*16 + g)*SA + kk + c];
                a[mi][0] = f2tf(p[0]);
                a[mi][1] = f2tf(p[8*SA]);
                a[mi][2] = f2tf(p[4]);
                a[mi][3] = f2tf(p[8*SA + 4]);
            }
            #pragma unroll
            for (int nj = 0; nj < 8; nj++) {
                const float* p = &Ws[buf][(wn*64 + nj*8 + g)*SA + kk + c];
                b[nj][0] = f2tf(p[0]);
                b[nj][1] = f2tf(p[4]);
            }
            #pragma unroll
            for (int mi = 0; mi < 2; mi++)
                #pragma unroll
                for (int nj = 0; nj < 8; nj++)
                    mma_tf32(acc[mi][nj], a[mi], b[nj], acc[mi][nj]);
        }
        __syncthreads();
    }

    // epilogue: bias (+RoPE for q,k), write [B,H,T,D]
    #pragma unroll
    for (int mi = 0; mi < 2; mi++) {
        #pragma unroll
        for (int rr = 0; rr < 2; rr++) {
            int m = m0 + wm*32 + mi*16 + g + rr*8;
            int b = m >> 11, t = m & (T_-1);
            #pragma unroll
            for (int nj = 0; nj < 8; nj++) {
                int n = n0 + wn*64 + nj*8 + 2*c;
                float v0 = acc[mi][nj][rr*2+0] + bias[n];
                float v1 = acc[mi][nj][rr*2+1] + bias[n+1];
                int h = n >> 6, d = n & 63;
                int base = ((b*H_+h)*T_+t)*D_ + d;
                if (which < 2) {
                    float c0 = g_cos[t*D_+d],   s0 = g_sin[t*D_+d];
                    float c1 = g_cos[t*D_+d+1], s1 = g_sin[t*D_+d+1];
                    dst[base]   = v0*c0 - v1*s0;
                    dst[base+1] = v1*c1 + v0*s1;
                } else {
                    dst[base]   = v0;
                    dst[base+1] = v1;
                }
            }
        }
    }
}

// ---------------- flash attention: tf32 mma, Q-tile 128, KV-tile 64 --------
#define KSS 68   // Ks row stride
#define VSS 72   // Vs row stride (conflict-free strided B-frag reads)
#define SSS 68   // Ss row stride
#define ATTN_SMEM ((2*64*KSS + 2*64*VSS + 128*SSS)*4)   // 106496 B

__global__ __launch_bounds__(256) void attn_kernel()
{
    extern __shared__ float sm[];
    float* Ks0 = sm;
    float* Ks1 = Ks0 + 64*KSS;
    float* Vs0 = Ks1 + 64*KSS;
    float* Vs1 = Vs0 + 64*VSS;
    float* Ss  = Vs1 + 64*VSS;
    float* KsB[2] = {Ks0, Ks1};
    float* VsB[2] = {Vs0, Vs1};

    int bh = blockIdx.y;
    int q0 = blockIdx.x * 128;
    const float* Q = g_q + bh*(T_*D_);
    const float* K = g_k + bh*(T_*D_);
    const float* V = g_v + bh*(T_*D_);
    int tid = threadIdx.x, lane = tid & 31, warp = tid >> 5;
    int g = lane >> 2, c = lane & 3;
    int row0 = q0 + warp*16;

    // preload Q fragments for all 8 k-steps (register-resident whole loop)
    uint32_t qa[8][4];
    #pragma unroll
    for (int ks = 0; ks < 8; ks++) {
        const float* p = Q + (row0+g)*D_ + ks*8 + c;
        qa[ks][0] = f2tf(p[0]);
        qa[ks][1] = f2tf(p[8*D_]);
        qa[ks][2] = f2tf(p[4]);
        qa[ks][3] = f2tf(p[8*D_+4]);
    }

    float o[8][4] = {};
    float mrun0 = -INFINITY, mrun1 = -INFINITY;
    float lrun0 = 0.f, lrun1 = 0.f;

    // prologue: kv tile 0
    #pragma unroll
    for (int i = 0; i < 4; i++) {
        int q = tid + i*256; int r = q >> 4, kc = q & 15;
        cpa16(&Ks0[r*KSS + kc*4], K + r*D_ + kc*4);
        cpa16(&Vs0[r*VSS + kc*4], V + r*D_ + kc*4);
    }
    CP_COMMIT;

    for (int kt = 0; kt < T_/64; ++kt) {
        int buf = kt & 1;
        if (kt + 1 < T_/64) {
            const float* Kn = K + (kt+1)*64*D_;
            const float* Vn = V + (kt+1)*64*D_;
            float* Kd = KsB[buf^1];
            float* Vd = VsB[buf^1];
            #pragma unroll
            for (int i = 0; i < 4; i++) {
                int q = tid + i*256; int r = q >> 4, kc = q & 15;
                cpa16(&Kd[r*KSS + kc*4], Kn + r*D_ + kc*4);
                cpa16(&Vd[r*VSS + kc*4], Vn + r*D_ + kc*4);
            }
            CP_COMMIT;
            CP_WAIT(1);
        } else {
            CP_WAIT(0);
        }
        __syncthreads();

        const float* Kc = KsB[buf];
        const float* Vc = VsB[buf];

        // S = Q K^T (16 rows/warp x 64 cols)
        float s[8][4] = {};
        #pragma unroll
        for (int ks = 0; ks < 8; ks++) {
            uint32_t b[8][2];
            #pragma unroll
            for (int nj = 0; nj < 8; nj++) {
                const float* p = &Kc[(nj*8+g)*KSS + ks*8 + c];
                b[nj][0] = f2tf(p[0]);
                b[nj][1] = f2tf(p[4]);
            }
            #pragma unroll
            for (int nj = 0; nj < 8; nj++)
                mma_tf32(s[nj], qa[ks], b[nj], s[nj]);
        }

        // scale + row stats (rows g, g+8 per thread; quad shfl reduce)
        float mx0 = -INFINITY, mx1 = -INFINITY;
        #pragma unroll
        for (int nj = 0; nj < 8; nj++) {
            s[nj][0] *= 0.125f; s[nj][1] *= 0.125f;
            s[nj][2] *= 0.125f; s[nj][3] *= 0.125f;
            mx0 = fmaxf(mx0, fmaxf(s[nj][0], s[nj][1]));
            mx1 = fmaxf(mx1, fmaxf(s[nj][2], s[nj][3]));
        }
        mx0 = fmaxf(mx0, __shfl_xor_sync(0xffffffffu, mx0, 1));
        mx0 = fmaxf(mx0, __shfl_xor_sync(0xffffffffu, mx0, 2));
        mx1 = fmaxf(mx1, __shfl_xor_sync(0xffffffffu, mx1, 1));
        mx1 = fmaxf(mx1, __shfl_xor_sync(0xffffffffu, mx1, 2));

        float nm0 = fmaxf(mrun0, mx0), nm1 = fmaxf(mrun1, mx1);
        float al0 = __expf(mrun0 - nm0), al1 = __expf(mrun1 - nm1);
        mrun0 = nm0; mrun1 = nm1;

        float sum0 = 0.f, sum1 = 0.f;
        #pragma unroll
        for (int nj = 0; nj < 8; nj++) {
            s[nj][0] = __expf(s[nj][0] - nm0);
            s[nj][1] = __expf(s[nj][1] - nm0);
            s[nj][2] = __expf(s[nj][2] - nm1);
            s[nj][3] = __expf(s[nj][3] - nm1);
            sum0 += s[nj][0] + s[nj][1];
            sum1 += s[nj][2] + s[nj][3];
        }
        sum0 += __shfl_xor_sync(0xffffffffu, sum0, 1);
        sum0 += __shfl_xor_sync(0xffffffffu, sum0, 2);
        sum1 += __shfl_xor_sync(0xffffffffu, sum1, 1);
        sum1 += __shfl_xor_sync(0xffffffffu, sum1, 2);
        lrun0 = lrun0*al0 + sum0;
        lrun1 = lrun1*al1 + sum1;

        #pragma unroll
        for (int nj = 0; nj < 8; nj++) {
            o[nj][0] *= al0; o[nj][1] *= al0;
            o[nj][2] *= al1; o[nj][3] *= al1;
        }

        // P -> smem (per-warp exclusive rows), then O += P V
        __syncwarp();
        #pragma unroll
        for (int nj = 0; nj < 8; nj++) {
            *(float2*)&Ss[(warp*16+g  )*SSS + nj*8 + 2*c] = make_float2(s[nj][0], s[nj][1]);
            *(float2*)&Ss[(warp*16+g+8)*SSS + nj*8 + 2*c] = make_float2(s[nj][2], s[nj][3]);
        }
        __syncwarp();

        #pragma unroll
        for (int ks2 = 0; ks2 < 8; ks2++) {
            uint32_t a[4];
            const float* p = &Ss[(warp*16+g)*SSS + ks2*8 + c];
            a[0] = f2tf(p[0]);
            a[1] = f2tf(p[8*SSS]);
            a[2] = f2tf(p[4]);
            a[3] = f2tf(p[8*SSS + 4]);
            #pragma unroll
            for (int dj = 0; dj < 8; dj++) {
                const float* pv = &Vc[(ks2*8+c)*VSS + dj*8 + g];
                uint32_t b2[2] = { f2tf(pv[0]), f2tf(pv[4*VSS]) };
                mma_tf32(o[dj], a, b2, o[dj]);
            }
        }
        __syncthreads();
    }

    float inv0 = 1.f / lrun0, inv1 = 1.f / lrun1;
    #pragma unroll
    for (int dj = 0; dj < 8; dj++) {
        int col = dj*8 + 2*c;
        float* p0 = g_att + (bh*T_ + row0 + g    )*D_ + col;
        float* p1 = g_att + (bh*T_ + row0 + g + 8)*D_ + col;
        *(float2*)p0 = make_float2(o[dj][0]*inv0, o[dj][1]*inv0);
        *(float2*)p1 = make_float2(o[dj][2]*inv1, o[dj][3]*inv1);
    }
}

// ---------------- output projection: tf32 mma, gathers [B,H,T,D] ------------
__global__ __launch_bounds__(256) void out_gemm_kernel(
    const float* __restrict__ Wo, const float* __restrict__ Bo,
    float* __restrict__ Out)
{
    __shared__ float As[2][128*SA];
    __shared__ float Bs[2][128*SA];
    int tid = threadIdx.x;
    int lane = tid & 31, warp = tid >> 5;
    int g = lane >> 2, c = lane & 3;
    int wm = warp & 3, wn = warp >> 2;
    int m0 = blockIdx.y * 128, n0 = blockIdx.x * 128;

    float acc[2][8][4] = {};

    #pragma unroll
    for (int i = 0; i < 2; i++) {
        int q = tid + i*256; int row = q >> 2, kc = q & 3;
        int m = m0 + row;  int b = m >> 11, t = m & (T_-1);
        int k = kc*4;      int h = k >> 6,  d = k & 63;
        cpa16(&As[0][row*SA + kc*4], g_att + ((b*H_+h)*T_ + t)*D_ + d);
        cpa16(&Bs[0][row*SA + kc*4], Wo + (n0+row)*C_ + kc*4);
    }
    CP_COMMIT;

    for (int it = 0; it < 64; ++it) {
        int buf = it & 1;
        if (it + 1 < 64) {
            int k0 = (it+1)*16, nb = buf ^ 1;
            #pragma unroll
            for (int i = 0; i < 2; i++) {
                int q = tid + i*256; int row = q >> 2, kc = q & 3;
                int m = m0 + row;      int b = m >> 11, t = m & (T_-1);
                int k = k0 + kc*4;     int h = k >> 6,  d = k & 63;
                cpa16(&As[nb][row*SA + kc*4], g_att + ((b*H_+h)*T_ + t)*D_ + d);
                cpa16(&Bs[nb][row*SA + kc*4], Wo + (n0+row)*C_ + k);
            }
            CP_COMMIT;
            CP_WAIT(1);
        } else {
            CP_WAIT(0);
        }
        __syncthreads();

        #pragma unroll
        for (int ks = 0; ks < 2; ks++) {
            int kk = ks*8;
            uint32_t a[2][4], b[8][2];
            #pragma unroll
            for (int mi = 0; mi < 2; mi++) {
                const float* p = &As[buf][(wm*32 + mi*16 + g)*SA + kk + c];
                a[mi][0] = f2tf(p[0]);
                a[mi][1] = f2tf(p[8*SA]);
                a[mi][2] = f2tf(p[4]);
                a[mi][3] = f2tf(p[8*SA + 4]);
            }
            #pragma unroll
            for (int nj = 0; nj < 8; nj++) {
                const float* p = &Bs[buf][(wn*64 + nj*8 + g)*SA + kk + c];
                b[nj][0] = f2tf(p[0]);
                b[nj][1] = f2tf(p[4]);
            }
            #pragma unroll
            for (int mi = 0; mi < 2; mi++)
                #pragma unroll
                for (int nj = 0; nj < 8; nj++)
                    mma_tf32(acc[mi][nj], a[mi], b[nj], acc[mi][nj]);
        }
        __syncthreads();
    }

    #pragma unroll
    for (int mi = 0; mi < 2; mi++) {
        #pragma unroll
        for (int rr = 0; rr < 2; rr++) {
            int m = m0 + wm*32 + mi*16 + g + rr*8;
            #pragma unroll
            for (int nj = 0; nj < 8; nj++) {
                int n = n0 + wn*64 + nj*8 + 2*c;
                float v0 = acc[mi][nj][rr*2+0] + Bo[n];
                float v1 = acc[mi][nj][rr*2+1] + Bo[n+1];
                *(float2*)&Out[m*C_ + n] = make_float2(v0, v1);
            }
        }
    }
}

// ---------------- launch ---------------------------------------------------
extern "C" void kernel_launch(void* const* d_in, const int* in_sizes, int n_in,
                              void* d_out, int out_size)
{
    const float* x  = (const float*)d_in[0];
    const float* wq = (const float*)d_in[1];
    const float* bq = (const float*)d_in[2];
    const float* wk = (const float*)d_in[3];
    const float* bk = (const float*)d_in[4];
    const float* wv = (const float*)d_in[5];
    const float* bv = (const float*)d_in[6];
    const float* wo = (const float*)d_in[7];
    const float* bo = (const float*)d_in[8];
    float* out = (float*)d_out;

    cudaFuncSetAttribute(attn_kernel,
                         cudaFuncAttributeMaxDynamicSharedMemorySize, ATTN_SMEM);

    rope_table_kernel<<<(T_*D_ + 255)/256, 256>>>();
    qkv_gemm_kernel<<<dim3(C_/128, M_/128, 3), 256>>>(x, wq, bq, wk, bk, wv, bv);
    attn_kernel<<<dim3(T_/128, B_*H_), 256, ATTN_SMEM>>>();
    out_gemm_kernel<<<dim3(C_/128, M_/128), 256>>>(wo, bo, out);
}

// round 4
// speedup vs baseline: 2.6327x; 1.0134x over previous
#include <cuda_runtime.h>
#include <math.h>
#include <stdint.h>

#define B_ 2
#define T_ 2048
#define C_ 1024
#define H_ 16
#define D_ 64
#define M_ (B_*T_)   // 4096

// ---------------- scratch (device globals; no allocation allowed) ----------
__device__ float g_q[B_*H_*T_*D_];     // [B,H,T,D] rotated Q * 0.125, tf32-rounded
__device__ float g_k[B_*H_*T_*D_];     // [B,H,T,D] rotated K, tf32-rounded
__device__ float g_v[B_*H_*T_*D_];     // [B,H,T,D] V, tf32-rounded
__device__ float g_att[B_*H_*T_*D_];   // [B,H,T,D] attention out, tf32-rounded
__device__ float g_x [M_*C_];          // X,  tf32-rounded
__device__ float g_wq[C_*C_];          // weights, tf32-rounded
__device__ float g_wk[C_*C_];
__device__ float g_wv[C_*C_];
__device__ float g_wo[C_*C_];
__device__ float g_cos[T_*D_];
__device__ float g_sin[T_*D_];

// ---------------- PTX helpers ----------------------------------------------
__device__ __forceinline__ uint32_t f2tf(float f) {
    uint32_t r;
    asm("cvt.rna.tf32.f32 %0, %1;" : "=r"(r) : "f"(f));
    return r;
}
__device__ __forceinline__ float tfr(float f) { return __uint_as_float(f2tf(f)); }

__device__ __forceinline__ void mma_tf32(float* d, const uint32_t* a,
                                         const uint32_t* b, const float* c) {
    asm volatile(
        "mma.sync.aligned.m16n8k8.row.col.f32.tf32.tf32.f32 "
        "{%0,%1,%2,%3}, {%4,%5,%6,%7}, {%8,%9}, {%10,%11,%12,%13};"
        : "=f"(d[0]), "=f"(d[1]), "=f"(d[2]), "=f"(d[3])
        : "r"(a[0]), "r"(a[1]), "r"(a[2]), "r"(a[3]),
          "r"(b[0]), "r"(b[1]),
          "f"(c[0]), "f"(c[1]), "f"(c[2]), "f"(c[3]));
}

__device__ __forceinline__ void cpa16(float* dst, const float* src) {
    uint32_t d = (uint32_t)__cvta_generic_to_shared(dst);
    asm volatile("cp.async.cg.shared.global [%0], [%1], 16;" :: "r"(d), "l"(src));
}
#define CP_COMMIT asm volatile("cp.async.commit_group;")
#define CP_WAIT(n) asm volatile("cp.async.wait_group %0;" :: "n"(n))

// ---------------- pre-convert inputs to tf32-rounded scratch ----------------
// float4 regions: X = 1048576, each W = 262144   (total 2097152 -> 8192 blocks)
__global__ __launch_bounds__(256) void preconvert_kernel(
    const float* __restrict__ X,  const float* __restrict__ Wq,
    const float* __restrict__ Wk, const float* __restrict__ Wv,
    const float* __restrict__ Wo)
{
    long i = (long)blockIdx.x*256 + threadIdx.x;
    const float4* src; float4* dst; long j;
    if      (i < 1048576)  { src=(const float4*)X;  dst=(float4*)g_x;  j=i; }
    else if (i < 1310720)  { src=(const float4*)Wq; dst=(float4*)g_wq; j=i-1048576; }
    else if (i < 1572864)  { src=(const float4*)Wk; dst=(float4*)g_wk; j=i-1310720; }
    else if (i < 1835008)  { src=(const float4*)Wv; dst=(float4*)g_wv; j=i-1572864; }
    else                   { src=(const float4*)Wo; dst=(float4*)g_wo; j=i-1835008; }
    float4 v = src[j];
    v.x = tfr(v.x); v.y = tfr(v.y); v.z = tfr(v.z); v.w = tfr(v.w);
    dst[j] = v;
}

// ---------------- RoPE tables ----------------------------------------------
__global__ void rope_table_kernel() {
    int idx = blockIdx.x * blockDim.x + threadIdx.x;
    if (idx >= T_*D_) return;
    int d = idx & (D_-1);
    int t = idx >> 6;
    int i = d & 31;
    double f = exp(-(double)(2*i) * (9.210340371976184 / 64.0));
    double a = (double)t * f;
    g_cos[idx] = (float)cos(a);
    g_sin[idx] = (float)sin(a);
}

// ---------------- QKV GEMM: tf32 mma, 128x128x16 tiles, fused RoPE ---------
#define SA 20   // smem row stride (floats): conflict-free fragment LDS

__global__ __launch_bounds__(256) void qkv_gemm_kernel(
    const float* __restrict__ Bq, const float* __restrict__ Bk,
    const float* __restrict__ Bv)
{
    __shared__ float Xs[2][128*SA];
    __shared__ float Ws[2][128*SA];
    const int which = blockIdx.z;
    const float* W    = (which==0) ? g_wq : (which==1) ? g_wk : g_wv;
    const float* bias = (which==0) ? Bq   : (which==1) ? Bk   : Bv;
    float* dst        = (which==0) ? g_q  : (which==1) ? g_k  : g_v;
    const float* X    = g_x;

    int tid = threadIdx.x;
    int lane = tid & 31, warp = tid >> 5;
    int g = lane >> 2, c = lane & 3;
    int wm = warp & 3, wn = warp >> 2;
    int m0 = blockIdx.y * 128, n0 = blockIdx.x * 128;

    float acc[2][8][4] = {};

    #pragma unroll
    for (int i = 0; i < 2; i++) {
        int q = tid + i*256; int row = q >> 2, kc = q & 3;
        cpa16(&Xs[0][row*SA + kc*4], X + (m0+row)*C_ + kc*4);
        cpa16(&Ws[0][row*SA + kc*4], W + (n0+row)*C_ + kc*4);
    }
    CP_COMMIT;

    for (int it = 0; it < 64; ++it) {
        int buf = it & 1;
        if (it + 1 < 64) {
            int k0 = (it+1)*16, nb = buf ^ 1;
            #pragma unroll
            for (int i = 0; i < 2; i++) {
                int q = tid + i*256; int row = q >> 2, kc = q & 3;
                cpa16(&Xs[nb][row*SA + kc*4], X + (m0+row)*C_ + k0 + kc*4);
                cpa16(&Ws[nb][row*SA + kc*4], W + (n0+row)*C_ + k0 + kc*4);
            }
            CP_COMMIT;
            CP_WAIT(1);
        } else {
            CP_WAIT(0);
        }
        __syncthreads();

        #pragma unroll
        for (int ks = 0; ks < 2; ks++) {
            int kk = ks*8;
            uint32_t a[2][4], b[8][2];
            #pragma unroll
            for (int mi = 0; mi < 2; mi++) {
                const float* p = &Xs[buf][(wm*32 + mi*16 + g)*SA + kk + c];
                a[mi][0] = __float_as_uint(p[0]);
                a[mi][1] = __float_as_uint(p[8*SA]);
                a[mi][2] = __float_as_uint(p[4]);
                a[mi][3] = __float_as_uint(p[8*SA + 4]);
            }
            #pragma unroll
            for (int nj = 0; nj < 8; nj++) {
                const float* p = &Ws[buf][(wn*64 + nj*8 + g)*SA + kk + c];
                b[nj][0] = __float_as_uint(p[0]);
                b[nj][1] = __float_as_uint(p[4]);
            }
            #pragma unroll
            for (int mi = 0; mi < 2; mi++)
                #pragma unroll
                for (int nj = 0; nj < 8; nj++)
                    mma_tf32(acc[mi][nj], a[mi], b[nj], acc[mi][nj]);
        }
        __syncthreads();
    }

    // epilogue: bias (+RoPE for q,k); q additionally scaled by 1/sqrt(D);
    // all outputs stored tf32-rounded
    #pragma unroll
    for (int mi = 0; mi < 2; mi++) {
        #pragma unroll
        for (int rr = 0; rr < 2; rr++) {
            int m = m0 + wm*32 + mi*16 + g + rr*8;
            int b = m >> 11, t = m & (T_-1);
            #pragma unroll
            for (int nj = 0; nj < 8; nj++) {
                int n = n0 + wn*64 + nj*8 + 2*c;
                float v0 = acc[mi][nj][rr*2+0] + bias[n];
                float v1 = acc[mi][nj][rr*2+1] + bias[n+1];
                int h = n >> 6, d = n & 63;
                int base = ((b*H_+h)*T_+t)*D_ + d;
                if (which < 2) {
                    float c0 = g_cos[t*D_+d],   s0 = g_sin[t*D_+d];
                    float c1 = g_cos[t*D_+d+1], s1 = g_sin[t*D_+d+1];
                    float r0 = v0*c0 - v1*s0;
                    float r1 = v1*c1 + v0*s1;
                    if (which == 0) { r0 *= 0.125f; r1 *= 0.125f; }
                    dst[base]   = tfr(r0);
                    dst[base+1] = tfr(r1);
                } else {
                    dst[base]   = tfr(v0);
                    dst[base+1] = tfr(v1);
                }
            }
        }
    }
}

// ---------------- flash attention: tf32 mma, Q-tile 128, KV-tile 64 --------
#define KSS 68   // Ks row stride
#define VSS 72   // Vs row stride (conflict-free strided B-frag reads)
#define SSS 68   // Ss row stride
#define ATTN_SMEM ((2*64*KSS + 2*64*VSS + 128*SSS)*4)   // 106496 B

__global__ __launch_bounds__(256) void attn_kernel()
{
    extern __shared__ float sm[];
    float* Ks0 = sm;
    float* Ks1 = Ks0 + 64*KSS;
    float* Vs0 = Ks1 + 64*KSS;
    float* Vs1 = Vs0 + 64*VSS;
    float* Ss  = Vs1 + 64*VSS;
    float* KsB[2] = {Ks0, Ks1};
    float* VsB[2] = {Vs0, Vs1};

    int bh = blockIdx.y;
    int q0 = blockIdx.x * 128;
    const float* Q = g_q + bh*(T_*D_);
    const float* K = g_k + bh*(T_*D_);
    const float* V = g_v + bh*(T_*D_);
    int tid = threadIdx.x, lane = tid & 31, warp = tid >> 5;
    int g = lane >> 2, c = lane & 3;
    int row0 = q0 + warp*16;

    // Q fragments: pre-rounded tf32 bits, register-resident whole loop
    uint32_t qa[8][4];
    #pragma unroll
    for (int ks = 0; ks < 8; ks++) {
        const float* p = Q + (row0+g)*D_ + ks*8 + c;
        qa[ks][0] = __float_as_uint(p[0]);
        qa[ks][1] = __float_as_uint(p[8*D_]);
        qa[ks][2] = __float_as_uint(p[4]);
        qa[ks][3] = __float_as_uint(p[8*D_+4]);
    }

    float o[8][4] = {};
    float mrun0 = -INFINITY, mrun1 = -INFINITY;
    float lrun0 = 0.f, lrun1 = 0.f;

    #pragma unroll
    for (int i = 0; i < 4; i++) {
        int q = tid + i*256; int r = q >> 4, kc = q & 15;
        cpa16(&Ks0[r*KSS + kc*4], K + r*D_ + kc*4);
        cpa16(&Vs0[r*VSS + kc*4], V + r*D_ + kc*4);
    }
    CP_COMMIT;

    for (int kt = 0; kt < T_/64; ++kt) {
        int buf = kt & 1;
        if (kt + 1 < T_/64) {
            const float* Kn = K + (kt+1)*64*D_;
            const float* Vn = V + (kt+1)*64*D_;
            float* Kd = KsB[buf^1];
            float* Vd = VsB[buf^1];
            #pragma unroll
            for (int i = 0; i < 4; i++) {
                int q = tid + i*256; int r = q >> 4, kc = q & 15;
                cpa16(&Kd[r*KSS + kc*4], Kn + r*D_ + kc*4);
                cpa16(&Vd[r*VSS + kc*4], Vn + r*D_ + kc*4);
            }
            CP_COMMIT;
            CP_WAIT(1);
        } else {
            CP_WAIT(0);
        }
        __syncthreads();

        const float* Kc = KsB[buf];
        const float* Vc = VsB[buf];

        // S = (Q/8) K^T  (scale pre-folded into Q)
        float s[8][4] = {};
        #pragma unroll
        for (int ks = 0; ks < 8; ks++) {
            uint32_t b[8][2];
            #pragma unroll
            for (int nj = 0; nj < 8; nj++) {
                const float* p = &Kc[(nj*8+g)*KSS + ks*8 + c];
                b[nj][0] = __float_as_uint(p[0]);
                b[nj][1] = __float_as_uint(p[4]);
            }
            #pragma unroll
            for (int nj = 0; nj < 8; nj++)
                mma_tf32(s[nj], qa[ks], b[nj], s[nj]);
        }

        // row stats (rows g, g+8 per thread; quad shfl reduce)
        float mx0 = -INFINITY, mx1 = -INFINITY;
        #pragma unroll
        for (int nj = 0; nj < 8; nj++) {
            mx0 = fmaxf(mx0, fmaxf(s[nj][0], s[nj][1]));
            mx1 = fmaxf(mx1, fmaxf(s[nj][2], s[nj][3]));
        }
        mx0 = fmaxf(mx0, __shfl_xor_sync(0xffffffffu, mx0, 1));
        mx0 = fmaxf(mx0, __shfl_xor_sync(0xffffffffu, mx0, 2));
        mx1 = fmaxf(mx1, __shfl_xor_sync(0xffffffffu, mx1, 1));
        mx1 = fmaxf(mx1, __shfl_xor_sync(0xffffffffu, mx1, 2));

        float nm0 = fmaxf(mrun0, mx0), nm1 = fmaxf(mrun1, mx1);
        float al0 = __expf(mrun0 - nm0), al1 = __expf(mrun1 - nm1);
        mrun0 = nm0; mrun1 = nm1;

        float sum0 = 0.f, sum1 = 0.f;
        #pragma unroll
        for (int nj = 0; nj < 8; nj++) {
            s[nj][0] = __expf(s[nj][0] - nm0);
            s[nj][1] = __expf(s[nj][1] - nm0);
            s[nj][2] = __expf(s[nj][2] - nm1);
            s[nj][3] = __expf(s[nj][3] - nm1);
            sum0 += s[nj][0] + s[nj][1];
            sum1 += s[nj][2] + s[nj][3];
        }
        sum0 += __shfl_xor_sync(0xffffffffu, sum0, 1);
        sum0 += __shfl_xor_sync(0xffffffffu, sum0, 2);
        sum1 += __shfl_xor_sync(0xffffffffu, sum1, 1);
        sum1 += __shfl_xor_sync(0xffffffffu, sum1, 2);
        lrun0 = lrun0*al0 + sum0;
        lrun1 = lrun1*al1 + sum1;

        #pragma unroll
        for (int nj = 0; nj < 8; nj++) {
            o[nj][0] *= al0; o[nj][1] *= al0;
            o[nj][2] *= al1; o[nj][3] *= al1;
        }

        // P -> smem tf32-rounded (per-warp exclusive rows), then O += P V
        __syncwarp();
        #pragma unroll
        for (int nj = 0; nj < 8; nj++) {
            *(float2*)&Ss[(warp*16+g  )*SSS + nj*8 + 2*c] =
                make_float2(tfr(s[nj][0]), tfr(s[nj][1]));
            *(float2*)&Ss[(warp*16+g+8)*SSS + nj*8 + 2*c] =
                make_float2(tfr(s[nj][2]), tfr(s[nj][3]));
        }
        __syncwarp();

        #pragma unroll
        for (int ks2 = 0; ks2 < 8; ks2++) {
            uint32_t a[4];
            const float* p = &Ss[(warp*16+g)*SSS + ks2*8 + c];
            a[0] = __float_as_uint(p[0]);
            a[1] = __float_as_uint(p[8*SSS]);
            a[2] = __float_as_uint(p[4]);
            a[3] = __float_as_uint(p[8*SSS + 4]);
            #pragma unroll
            for (int dj = 0; dj < 8; dj++) {
                const float* pv = &Vc[(ks2*8+c)*VSS + dj*8 + g];
                uint32_t b2[2] = { __float_as_uint(pv[0]), __float_as_uint(pv[4*VSS]) };
                mma_tf32(o[dj], a, b2, o[dj]);
            }
        }
        __syncthreads();
    }

    float inv0 = 1.f / lrun0, inv1 = 1.f / lrun1;
    #pragma unroll
    for (int dj = 0; dj < 8; dj++) {
        int col = dj*8 + 2*c;
        float* p0 = g_att + (bh*T_ + row0 + g    )*D_ + col;
        float* p1 = g_att + (bh*T_ + row0 + g + 8)*D_ + col;
        *(float2*)p0 = make_float2(tfr(o[dj][0]*inv0), tfr(o[dj][1]*inv0));
        *(float2*)p1 = make_float2(tfr(o[dj][2]*inv1), tfr(o[dj][3]*inv1));
    }
}

// ---------------- output projection: tf32 mma, gathers [B,H,T,D] ------------
__global__ __launch_bounds__(256) void out_gemm_kernel(
    const float* __restrict__ Bo, float* __restrict__ Out)
{
    __shared__ float As[2][128*SA];
    __shared__ float Bs[2][128*SA];
    int tid = threadIdx.x;
    int lane = tid & 31, warp = tid >> 5;
    int g = lane >> 2, c = lane & 3;
    int wm = warp & 3, wn = warp >> 2;
    int m0 = blockIdx.y * 128, n0 = blockIdx.x * 128;

    float acc[2][8][4] = {};

    #pragma unroll
    for (int i = 0; i < 2; i++) {
        int q = tid + i*256; int row = q >> 2, kc = q & 3;
        int m = m0 + row;  int b = m >> 11, t = m & (T_-1);
        int k = kc*4;      int h = k >> 6,  d = k & 63;
        cpa16(&As[0][row*SA + kc*4], g_att + ((b*H_+h)*T_ + t)*D_ + d);
        cpa16(&Bs[0][row*SA + kc*4], g_wo + (n0+row)*C_ + kc*4);
    }
    CP_COMMIT;

    for (int it = 0; it < 64; ++it) {
        int buf = it & 1;
        if (it + 1 < 64) {
            int k0 = (it+1)*16, nb = buf ^ 1;
            #pragma unroll
            for (int i = 0; i < 2; i++) {
                int q = tid + i*256; int row = q >> 2, kc = q & 3;
                int m = m0 + row;      int b = m >> 11, t = m & (T_-1);
                int k = k0 + kc*4;     int h = k >> 6,  d = k & 63;
                cpa16(&As[nb][row*SA + kc*4], g_att + ((b*H_+h)*T_ + t)*D_ + d);
                cpa16(&Bs[nb][row*SA + kc*4], g_wo + (n0+row)*C_ + k);
            }
            CP_COMMIT;
            CP_WAIT(1);
        } else {
            CP_WAIT(0);
        }
        __syncthreads();

        #pragma unroll
        for (int ks = 0; ks < 2; ks++) {
            int kk = ks*8;
            uint32_t a[2][4], b[8][2];
            #pragma unroll
            for (int mi = 0; mi < 2; mi++) {
                const float* p = &As[buf][(wm*32 + mi*16 + g)*SA + kk + c];
                a[mi][0] = __float_as_uint(p[0]);
                a[mi][1] = __float_as_uint(p[8*SA]);
                a[mi][2] = __float_as_uint(p[4]);
                a[mi][3] = __float_as_uint(p[8*SA + 4]);
            }
            #pragma unroll
            for (int nj = 0; nj < 8; nj++) {
                const float* p = &Bs[buf][(wn*64 + nj*8 + g)*SA + kk + c];
                b[nj][0] = __float_as_uint(p[0]);
                b[nj][1] = __float_as_uint(p[4]);
            }
            #pragma unroll
            for (int mi = 0; mi < 2; mi++)
                #pragma unroll
                for (int nj = 0; nj < 8; nj++)
                    mma_tf32(acc[mi][nj], a[mi], b[nj], acc[mi][nj]);
        }
        __syncthreads();
    }

    #pragma unroll
    for (int mi = 0; mi < 2; mi++) {
        #pragma unroll
        for (int rr = 0; rr < 2; rr++) {
            int m = m0 + wm*32 + mi*16 + g + rr*8;
            #pragma unroll
            for (int nj = 0; nj < 8; nj++) {
                int n = n0 + wn*64 + nj*8 + 2*c;
                float v0 = acc[mi][nj][rr*2+0] + Bo[n];
                float v1 = acc[mi][nj][rr*2+1] + Bo[n+1];
                *(float2*)&Out[m*C_ + n] = make_float2(v0, v1);
            }
        }
    }
}

// ---------------- launch ---------------------------------------------------
extern "C" void kernel_launch(void* const* d_in, const int* in_sizes, int n_in,
                              void* d_out, int out_size)
{
    const float* x  = (const float*)d_in[0];
    const float* wq = (const float*)d_in[1];
    const float* bq = (const float*)d_in[2];
    const float* wk = (const float*)d_in[3];
    const float* bk = (const float*)d_in[4];
    const float* wv = (const float*)d_in[5];
    const float* bv = (const float*)d_in[6];
    const float* wo = (const float*)d_in[7];
    const float* bo = (const float*)d_in[8];
    float* out = (float*)d_out;

    cudaFuncSetAttribute(attn_kernel,
                         cudaFuncAttributeMaxDynamicSharedMemorySize, ATTN_SMEM);

    preconvert_kernel<<<8192, 256>>>(x, wq, wk, wv, wo);
    rope_table_kernel<<<(T_*D_ + 255)/256, 256>>>();
    qkv_gemm_kernel<<<dim3(C_/128, M_/128, 3), 256>>>(bq, bk, bv);
    attn_kernel<<<dim3(T_/128, B_*H_), 256, ATTN_SMEM>>>();
    out_gemm_kernel<<<dim3(C_/128, M_/128), 256>>>(bo, out);
}